// round 3
// baseline (speedup 1.0000x reference)
#include <cuda_runtime.h>
#include <cuda_bf16.h>
#include <math.h>

// Problem constants
#define BB 32
#define TT 2048
#define HH 128
// rows per block for the projection GEMM
#define ROWS 64

// Scratch (no cudaMalloc allowed): xp buffer (reused by both layers) and layer-0 output.
__device__ float g_xp[BB * TT * HH];
__device__ float g_h0[BB * TT * HH];

// -----------------------------------------------------------------------------
// Input projection: out[n, j] = sum_k X[n,k] * W[k,j] + bias[j]
// If X == nullptr, rows are gathered from emb via tokens (layer-0 path).
// Block: 128 threads (thread = output column j), ROWS rows per block.
// -----------------------------------------------------------------------------
__global__ __launch_bounds__(128) void inproj_kernel(
    const float* __restrict__ X,      // dense input [N,128] or nullptr
    const int*   __restrict__ tokens, // [N] (used when X == nullptr)
    const float* __restrict__ emb,    // [VOCAB,128]
    const float* __restrict__ W,      // [128,128]
    const float* __restrict__ bias,   // [128]
    float* __restrict__ out)          // [N,128]
{
    __shared__ float xs[ROWS][HH];
    const int j = threadIdx.x;

    // Column j of W into registers (loads coalesced across threads).
    float w[HH];
#pragma unroll
    for (int k = 0; k < HH; k++) w[k] = W[k * HH + j];
    const float bj = bias[j];

    const size_t base = (size_t)blockIdx.x * ROWS;

    // Cooperative load of ROWS input rows into shared.
    for (int idx = j; idx < ROWS * HH; idx += 128) {
        const int r = idx >> 7;
        const int k = idx & 127;
        float v;
        if (X) {
            v = X[(base + r) * HH + k];
        } else {
            v = emb[(size_t)tokens[base + r] * HH + k];
        }
        xs[r][k] = v;
    }
    __syncthreads();

    for (int r = 0; r < ROWS; r++) {
        float a0 = bj, a1 = 0.f, a2 = 0.f, a3 = 0.f;
        const float4* x4 = (const float4*)xs[r];
#pragma unroll
        for (int k = 0; k < HH; k += 4) {
            float4 xv = x4[k >> 2];          // broadcast LDS (all threads same addr)
            a0 = fmaf(xv.x, w[k    ], a0);
            a1 = fmaf(xv.y, w[k + 1], a1);
            a2 = fmaf(xv.z, w[k + 2], a2);
            a3 = fmaf(xv.w, w[k + 3], a3);
        }
        out[(base + r) * HH + j] = (a0 + a1) + (a2 + a3);
    }
}

// -----------------------------------------------------------------------------
// Masked SimpleRNN recurrence: one block per batch element, thread j owns h[j].
//   h_new = tanh(xp[t,j] + sum_k h[k] * Wh[k,j]);  h = mask ? h_new : h
// Wh column j lives in registers; h double-buffered in shared (1 barrier/step);
// next step's xp/token prefetched to hide L2 latency under the FMA loop.
// -----------------------------------------------------------------------------
__global__ __launch_bounds__(128, 1) void rnn_rec_kernel(
    const float* __restrict__ xp,     // [B,T,128] precomputed input projection
    const int*   __restrict__ tokens, // [B,T]
    const float* __restrict__ Wh,     // [128,128]
    float* __restrict__ out)          // [B,T,128]
{
    const int b = blockIdx.x;
    const int j = threadIdx.x;

    __shared__ float hsh[2][HH];

    float w[HH];
#pragma unroll
    for (int k = 0; k < HH; k++) w[k] = Wh[k * HH + j];

    hsh[0][j] = 0.f;
    float h = 0.f;
    __syncthreads();

    const float* xpb = xp + (size_t)b * TT * HH;
    const int*   tkb = tokens + (size_t)b * TT;
    float* outb = out + (size_t)b * TT * HH;

    int cur = 0;
    float xv  = xpb[j];
    int   tok = tkb[0];

    for (int t = 0; t < TT; t++) {
        // Prefetch next step's inputs before the compute loop.
        float xv_n = 0.f;
        int   tok_n = 0;
        if (t + 1 < TT) {
            xv_n  = xpb[(t + 1) * HH + j];
            tok_n = tkb[t + 1];
        }

        float a0 = 0.f, a1 = 0.f, a2 = 0.f, a3 = 0.f;
        const float4* h4 = (const float4*)hsh[cur];
#pragma unroll
        for (int k = 0; k < HH; k += 4) {
            float4 hv = h4[k >> 2];
            a0 = fmaf(hv.x, w[k    ], a0);
            a1 = fmaf(hv.y, w[k + 1], a1);
            a2 = fmaf(hv.z, w[k + 2], a2);
            a3 = fmaf(hv.w, w[k + 3], a3);
        }

        const float hn = tanhf(xv + ((a0 + a1) + (a2 + a3)));
        h = (tok != 0) ? hn : h;

        outb[t * HH + j] = h;

        cur ^= 1;
        hsh[cur][j] = h;
        __syncthreads();

        xv  = xv_n;
        tok = tok_n;
    }
}

// -----------------------------------------------------------------------------
// kernel_launch
// Inputs (metadata order): tokens int32 [32,2048], emb f32 [32000,128],
//   Wx0 [128,128], Wh0 [128,128], b0 [128], Wx1 [128,128], Wh1 [128,128], b1 [128]
// Output: f32 [32,2048,128]
// -----------------------------------------------------------------------------
extern "C" void kernel_launch(void* const* d_in, const int* in_sizes, int n_in,
                              void* d_out, int out_size)
{
    const int*   tokens = (const int*)  d_in[0];
    const float* emb    = (const float*)d_in[1];
    const float* Wx0    = (const float*)d_in[2];
    const float* Wh0    = (const float*)d_in[3];
    const float* b0     = (const float*)d_in[4];
    const float* Wx1    = (const float*)d_in[5];
    const float* Wh1    = (const float*)d_in[6];
    const float* b1     = (const float*)d_in[7];
    float* out = (float*)d_out;

    float* xp = nullptr;
    float* h0 = nullptr;
    cudaGetSymbolAddress((void**)&xp, g_xp);
    cudaGetSymbolAddress((void**)&h0, g_h0);

    const int nrows = BB * TT;           // 65536
    const int nblk  = nrows / ROWS;      // 1024

    // Layer 0: xp0 = gather(emb, tokens) @ Wx0 + b0
    inproj_kernel<<<nblk, 128>>>(nullptr, tokens, emb, Wx0, b0, xp);
    // Layer 0 recurrence -> h0
    rnn_rec_kernel<<<BB, 128>>>(xp, tokens, Wh0, h0);
    // Layer 1: xp1 = h0 @ Wx1 + b1 (reuse xp buffer)
    inproj_kernel<<<nblk, 128>>>(h0, tokens, emb, Wx1, b1, xp);
    // Layer 1 recurrence -> output
    rnn_rec_kernel<<<BB, 128>>>(xp, tokens, Wh1, out);
}

// round 4
// speedup vs baseline: 1.0554x; 1.0554x over previous
#include <cuda_runtime.h>
#include <cuda_bf16.h>
#include <math.h>

// Problem constants
#define BB 32
#define TT 2048
#define HH 128
// rows per block for the projection GEMM
#define ROWS 64

// Scratch (no cudaMalloc allowed): xp buffer (reused by both layers) and layer-0 output.
__device__ float g_xp[BB * TT * HH];
__device__ float g_h0[BB * TT * HH];

// -----------------------------------------------------------------------------
// Input projection: out[n, j] = sum_k X[n,k] * W[k,j] + bias[j]
// If X == nullptr, rows are gathered from emb via tokens (layer-0 path).
// Block: 128 threads (thread = output column j), ROWS rows per block.
// -----------------------------------------------------------------------------
__global__ __launch_bounds__(128) void inproj_kernel(
    const float* __restrict__ X,      // dense input [N,128] or nullptr
    const int*   __restrict__ tokens, // [N] (used when X == nullptr)
    const float* __restrict__ emb,    // [VOCAB,128]
    const float* __restrict__ W,      // [128,128]
    const float* __restrict__ bias,   // [128]
    float* __restrict__ out)          // [N,128]
{
    __shared__ float xs[ROWS][HH];
    const int j = threadIdx.x;

    // Column j of W into registers (loads coalesced across threads).
    float w[HH];
#pragma unroll
    for (int k = 0; k < HH; k++) w[k] = W[k * HH + j];
    const float bj = bias[j];

    const size_t base = (size_t)blockIdx.x * ROWS;

    // Cooperative load of ROWS input rows into shared.
    for (int idx = j; idx < ROWS * HH; idx += 128) {
        const int r = idx >> 7;
        const int k = idx & 127;
        float v;
        if (X) {
            v = X[(base + r) * HH + k];
        } else {
            v = emb[(size_t)tokens[base + r] * HH + k];
        }
        xs[r][k] = v;
    }
    __syncthreads();

    for (int r = 0; r < ROWS; r++) {
        float a0 = bj, a1 = 0.f, a2 = 0.f, a3 = 0.f;
        const float4* x4 = (const float4*)xs[r];
#pragma unroll
        for (int k = 0; k < HH; k += 4) {
            float4 xv = x4[k >> 2];          // broadcast LDS (all threads same addr)
            a0 = fmaf(xv.x, w[k    ], a0);
            a1 = fmaf(xv.y, w[k + 1], a1);
            a2 = fmaf(xv.z, w[k + 2], a2);
            a3 = fmaf(xv.w, w[k + 3], a3);
        }
        out[(base + r) * HH + j] = (a0 + a1) + (a2 + a3);
    }
}

// -----------------------------------------------------------------------------
// Masked SimpleRNN recurrence: one block per batch element, thread j owns h[j].
//   h_new = tanh(xp[t,j] + sum_k h[k] * Wh[k,j]);  h = mask ? h_new : h
// Wh column j lives in registers; h double-buffered in shared (1 barrier/step);
// next step's xp/token prefetched to hide L2 latency under the FMA loop.
// -----------------------------------------------------------------------------
__global__ __launch_bounds__(128, 1) void rnn_rec_kernel(
    const float* __restrict__ xp,     // [B,T,128] precomputed input projection
    const int*   __restrict__ tokens, // [B,T]
    const float* __restrict__ Wh,     // [128,128]
    float* __restrict__ out)          // [B,T,128]
{
    const int b = blockIdx.x;
    const int j = threadIdx.x;

    __shared__ float hsh[2][HH];

    float w[HH];
#pragma unroll
    for (int k = 0; k < HH; k++) w[k] = Wh[k * HH + j];

    hsh[0][j] = 0.f;
    float h = 0.f;
    __syncthreads();

    const float* xpb = xp + (size_t)b * TT * HH;
    const int*   tkb = tokens + (size_t)b * TT;
    float* outb = out + (size_t)b * TT * HH;

    int cur = 0;
    float xv  = xpb[j];
    int   tok = tkb[0];

    for (int t = 0; t < TT; t++) {
        // Prefetch next step's inputs before the compute loop.
        float xv_n = 0.f;
        int   tok_n = 0;
        if (t + 1 < TT) {
            xv_n  = xpb[(t + 1) * HH + j];
            tok_n = tkb[t + 1];
        }

        float a0 = 0.f, a1 = 0.f, a2 = 0.f, a3 = 0.f;
        const float4* h4 = (const float4*)hsh[cur];
#pragma unroll
        for (int k = 0; k < HH; k += 4) {
            float4 hv = h4[k >> 2];
            a0 = fmaf(hv.x, w[k    ], a0);
            a1 = fmaf(hv.y, w[k + 1], a1);
            a2 = fmaf(hv.z, w[k + 2], a2);
            a3 = fmaf(hv.w, w[k + 3], a3);
        }

        const float hn = tanhf(xv + ((a0 + a1) + (a2 + a3)));
        h = (tok != 0) ? hn : h;

        outb[t * HH + j] = h;

        cur ^= 1;
        hsh[cur][j] = h;
        __syncthreads();

        xv  = xv_n;
        tok = tok_n;
    }
}

// -----------------------------------------------------------------------------
// kernel_launch
// Inputs (metadata order): tokens int32 [32,2048], emb f32 [32000,128],
//   Wx0 [128,128], Wh0 [128,128], b0 [128], Wx1 [128,128], Wh1 [128,128], b1 [128]
// Output: f32 [32,2048,128]
// -----------------------------------------------------------------------------
extern "C" void kernel_launch(void* const* d_in, const int* in_sizes, int n_in,
                              void* d_out, int out_size)
{
    const int*   tokens = (const int*)  d_in[0];
    const float* emb    = (const float*)d_in[1];
    const float* Wx0    = (const float*)d_in[2];
    const float* Wh0    = (const float*)d_in[3];
    const float* b0     = (const float*)d_in[4];
    const float* Wx1    = (const float*)d_in[5];
    const float* Wh1    = (const float*)d_in[6];
    const float* b1     = (const float*)d_in[7];
    float* out = (float*)d_out;

    float* xp = nullptr;
    float* h0 = nullptr;
    cudaGetSymbolAddress((void**)&xp, g_xp);
    cudaGetSymbolAddress((void**)&h0, g_h0);

    const int nrows = BB * TT;           // 65536
    const int nblk  = nrows / ROWS;      // 1024

    // Layer 0: xp0 = gather(emb, tokens) @ Wx0 + b0
    inproj_kernel<<<nblk, 128>>>(nullptr, tokens, emb, Wx0, b0, xp);
    // Layer 0 recurrence -> h0
    rnn_rec_kernel<<<BB, 128>>>(xp, tokens, Wh0, h0);
    // Layer 1: xp1 = h0 @ Wx1 + b1 (reuse xp buffer)
    inproj_kernel<<<nblk, 128>>>(h0, tokens, emb, Wx1, b1, xp);
    // Layer 1 recurrence -> output
    rnn_rec_kernel<<<BB, 128>>>(xp, tokens, Wh1, out);
}